// round 17
// baseline (speedup 1.0000x reference)
#include <cuda_runtime.h>

// decoder_fm — R17: single-wave bulk-gather pipeline.
// Established floor: ~65K scattered 256B reads are DRAM activation-limited at
// ~1.5TB/s (~10.5us) on every path (LDG/TMA/prefetch). This round removes the
// remaining non-floor costs: grid=128 CTAs (all resident, single wave, zero
// wave transitions), each CTA bulk-copies its 128 rows (256 copies) up-front
// so the full request stream is in flight at t~0; completion split across two
// mbarrier stages (64 rows each) so stage-0 math overlaps stage-1 arrival.
// SMEM row stride 320B -> conflict-free LDS.128. Known-good R7 math.

#define PACK2(d, lo, hi)   asm("mov.b64 %0, {%1, %2};" : "=l"(d) : "f"(lo), "f"(hi))
#define UNPACK2(lo, hi, s) asm("mov.b64 {%0, %1}, %2;" : "=f"(lo), "=f"(hi) : "l"(s))
#define FMA2(d, a, b)      asm("fma.rn.f32x2 %0, %1, %2, %3;" : "=l"(d) : "l"(a), "l"(b), "l"(d))
#define ADD2(d, a, b)      asm("add.rn.f32x2 %0, %1, %2;" : "=l"(d) : "l"(a), "l"(b))

__device__ __forceinline__ unsigned smem_u32(const void* p) {
    unsigned a;
    asm("{ .reg .u64 t; cvta.to.shared.u64 t, %1; cvt.u32.u64 %0, t; }" : "=r"(a) : "l"(p));
    return a;
}

__device__ __forceinline__ void mbar_wait(unsigned mb) {
    unsigned done;
    asm volatile(
        "{\n\t.reg .pred p;\n\t"
        "mbarrier.try_wait.parity.acquire.cta.shared::cta.b64 p, [%1], 0;\n\t"
        "selp.b32 %0, 1, 0, p;\n\t}"
        : "=r"(done) : "r"(mb) : "memory");
    if (!done) {
        asm volatile(
            "{\n\t.reg .pred P1;\n\t"
            "WL_%=:\n\t"
            "mbarrier.try_wait.parity.acquire.cta.shared::cta.b64 P1, [%0], 0, 0x989680;\n\t"
            "@P1 bra.uni WD_%=;\n\t"
            "bra.uni WL_%=;\n\t"
            "WD_%=:\n\t}"
            :: "r"(mb) : "memory");
    }
}

#define XSTRIDE 80   // floats per row half-buffer slot (320B) -> conflict-free LDS

// dynamic smem layout (floats):
//   [0,256)        sws  : float2[128]  (fc_w[j], s_j)
//   [256,1536)     sV   : float2[5][128]
//   [1536,1792)    sidx : int[256]   (128 user idx, 128 item idx)
//   [1792,12032)   sxu  : 128 rows x 80 floats (user halves, 256B used)
//   [12032,22272)  sxi  : 128 rows x 80 floats (item halves)
//   [22272,22276)  mbar : 2 x u64
#define SMEM_FLOATS 22280
#define SMEM_BYTES  (SMEM_FLOATS * 4)

__global__ __launch_bounds__(256) void fm_kernel(
    const int* __restrict__ user, const int* __restrict__ item,
    const float* __restrict__ user_emb, const float* __restrict__ item_emb,
    const float* __restrict__ fc_w, const float* __restrict__ fc_b,
    const float* __restrict__ fm_V,
    const float* __restrict__ b_users, const float* __restrict__ b_items,
    float* __restrict__ out, int nrows)
{
    extern __shared__ __align__(16) float smem[];
    float2* sws = reinterpret_cast<float2*>(smem);           // 128
    float2* sV  = reinterpret_cast<float2*>(smem + 256);     // [k2*128 + j]
    int*    sidx = reinterpret_cast<int*>(smem + 1536);      // 256
    float*  sxu  = smem + 1792;
    float*  sxi  = smem + 12032;
    unsigned long long* mbar = reinterpret_cast<unsigned long long*>(smem + 22272);

    const int tid = threadIdx.x;
    const int blockBase = blockIdx.x * 128;
    const int rowsHere  = min(128, nrows - blockBase);
    const int s0 = min(64, rowsHere);
    const int s1 = rowsHere - s0;           // may be 0

    // ---- init mbarriers + stage indices (coalesced) ----
    if (tid == 0) {
        asm volatile("mbarrier.init.shared.b64 [%0], 1;" :: "r"(smem_u32(&mbar[0])) : "memory");
        asm volatile("mbarrier.init.shared.b64 [%0], 1;" :: "r"(smem_u32(&mbar[1])) : "memory");
    }
    if (tid < 128) {
        sidx[tid] = (tid < rowsHere) ? user[blockBase + tid] : 0;
    } else {
        const int r = tid - 128;
        sidx[tid] = (r < rowsHere) ? item[blockBase + r] : 0;
    }

    // ---- param staging (overlaps index latency) ----
    if (tid < 128) {
        float v[10];
        #pragma unroll
        for (int k = 0; k < 10; k++) v[k] = fm_V[tid * 10 + k];
        float s = 0.f;
        #pragma unroll
        for (int k = 0; k < 10; k++) s = fmaf(v[k], v[k], s);
        sws[tid] = make_float2(fc_w[tid], s);
        #pragma unroll
        for (int k2 = 0; k2 < 5; k2++)
            sV[k2 * 128 + tid] = make_float2(v[2 * k2], v[2 * k2 + 1]);
    }
    __syncthreads();   // sidx + mbar init visible

    // ---- issue ALL 256B bulk copies up front: thread t -> row t>>1, half t&1 ----
    if (tid < 2 * rowsHere) {
        const int r    = tid >> 1;
        const int half = tid & 1;
        const int idx  = half ? sidx[128 + r] : sidx[r];
        const float* src = (half ? item_emb : user_emb) + (long long)idx * 64;
        float* dstf = (half ? sxi : sxu) + r * XSTRIDE;
        const unsigned dst = smem_u32(dstf);
        const unsigned mb  = smem_u32(&mbar[r >> 6]);
        asm volatile(
            "cp.async.bulk.shared::cluster.global.mbarrier::complete_tx::bytes "
            "[%0], [%1], %2, [%3];"
            :: "r"(dst), "l"(src), "r"(256u), "r"(mb) : "memory");
    }
    if (tid == 0) {
        asm volatile("mbarrier.arrive.expect_tx.shared.b64 _, [%0], %1;"
                     :: "r"(smem_u32(&mbar[0])), "r"((unsigned)(s0 * 512)) : "memory");
        asm volatile("mbarrier.arrive.expect_tx.shared.b64 _, [%0], %1;"
                     :: "r"(smem_u32(&mbar[1])), "r"((unsigned)(s1 * 512)) : "memory");
    }

    // ---- per-row scalars for BOTH stages, issued before any wait ----
    const int lane = tid & 31;
    const int sub  = lane & 3;
    const int rw   = lane >> 2;
    const int warp = tid >> 5;          // 0..7
    const int rA = warp * 8 + rw;       // stage-0 row (0..63)
    const int rB = 64 + rA;             // stage-1 row (64..127)

    float bu0 = 0.f, bi0 = 0.f, bu1 = 0.f, bi1 = 0.f, fb = 0.f;
    if (sub == 0) {
        fb = __ldg(fc_b);
        if (rA < rowsHere) {
            bu0 = __ldg(b_users + sidx[rA]);
            bi0 = __ldg(b_items + sidx[128 + rA]);
        }
        if (rB < rowsHere) {
            bu1 = __ldg(b_users + sidx[rB]);
            bi1 = __ldg(b_items + sidx[128 + rB]);
        }
    }

    // ---- two stages: wait, compute, store ----
    #pragma unroll
    for (int stage = 0; stage < 2; stage++) {
        mbar_wait(smem_u32(&mbar[stage]));

        const int rowL = stage ? rB : rA;
        if (rowL >= rowsHere) continue;

        const float* xu = sxu + rowL * XSTRIDE;
        const float* xi = sxi + rowL * XSTRIDE;

        unsigned long long acc_ls = 0ull;
        unsigned long long acc2[5];
        #pragma unroll
        for (int k2 = 0; k2 < 5; k2++) acc2[k2] = 0ull;

        #pragma unroll
        for (int h = 0; h < 2; h++) {
            const float* xh = h ? xi : xu;
            #pragma unroll
            for (int c = 0; c < 4; c++) {
                const int jl = (c * 4 + sub) * 4;     // 0..60 within half
                const int j0 = h * 64 + jl;
                const float4 xq = *reinterpret_cast<const float4*>(xh + jl);
                const float xs[4] = {xq.x, xq.y, xq.z, xq.w};

                const ulonglong2 wsA = *reinterpret_cast<const ulonglong2*>(&sws[j0]);
                const ulonglong2 wsB = *reinterpret_cast<const ulonglong2*>(&sws[j0 + 2]);
                const unsigned long long wsp[4] = {wsA.x, wsA.y, wsB.x, wsB.y};

                ulonglong2 vA[5], vB[5];
                #pragma unroll
                for (int k2 = 0; k2 < 5; k2++) {
                    vA[k2] = *reinterpret_cast<const ulonglong2*>(&sV[k2 * 128 + j0]);
                    vB[k2] = *reinterpret_cast<const ulonglong2*>(&sV[k2 * 128 + j0 + 2]);
                }

                #pragma unroll
                for (int jj = 0; jj < 4; jj++) {
                    const float x = xs[jj];
                    unsigned long long xp, xsq;
                    PACK2(xp,  x, x);
                    PACK2(xsq, x, x * x);
                    FMA2(acc_ls, xsq, wsp[jj]);        // lin += x*w ; x2s += x^2*s
                    #pragma unroll
                    for (int k2 = 0; k2 < 5; k2++) {
                        const unsigned long long vj =
                            (jj == 0) ? vA[k2].x : (jj == 1) ? vA[k2].y
                                     : (jj == 2) ? vB[k2].x : vB[k2].y;
                        FMA2(acc2[k2], xp, vj);
                    }
                }
            }
        }

        #pragma unroll
        for (int m = 1; m <= 2; m <<= 1) {
            unsigned long long t;
            t = __shfl_xor_sync(0xFFFFFFFFu, acc_ls, m); ADD2(acc_ls, acc_ls, t);
            #pragma unroll
            for (int k2 = 0; k2 < 5; k2++) {
                t = __shfl_xor_sync(0xFFFFFFFFu, acc2[k2], m); ADD2(acc2[k2], acc2[k2], t);
            }
        }

        if (sub == 0) {
            float xv0, xv1, lin, x2s;
            UNPACK2(lin, x2s, acc_ls);
            float inter = -x2s;
            #pragma unroll
            for (int k2 = 0; k2 < 5; k2++) {
                UNPACK2(xv0, xv1, acc2[k2]);
                inter = fmaf(xv0, xv0, inter);
                inter = fmaf(xv1, xv1, inter);
            }
            const float bu = stage ? bu1 : bu0;
            const float bi = stage ? bi1 : bi0;
            out[blockBase + rowL] = 0.5f * inter + lin + fb + bu + bi + 4.0f;
        }
    }
}

extern "C" void kernel_launch(void* const* d_in, const int* in_sizes, int n_in,
                              void* d_out, int out_size)
{
    // metadata order: user, item, u_out, i_out, user_emb, item_emb,
    //                 fc_w, fc_b, fm_V, b_users, b_items
    const int*   user     = (const int*)d_in[0];
    const int*   item     = (const int*)d_in[1];
    const float* user_emb = (const float*)d_in[4];
    const float* item_emb = (const float*)d_in[5];
    const float* fc_w     = (const float*)d_in[6];
    const float* fc_b     = (const float*)d_in[7];
    const float* fm_V     = (const float*)d_in[8];
    const float* b_users  = (const float*)d_in[9];
    const float* b_items  = (const float*)d_in[10];
    float* out = (float*)d_out;

    cudaFuncSetAttribute(fm_kernel, cudaFuncAttributeMaxDynamicSharedMemorySize,
                         SMEM_BYTES);

    const int nrows = in_sizes[0];
    const int grid  = (nrows + 127) / 128;   // 128 rows per CTA -> single wave
    fm_kernel<<<grid, 256, SMEM_BYTES>>>(user, item, user_emb, item_emb,
                                         fc_w, fc_b, fm_V, b_users, b_items,
                                         out, nrows);
}